// round 6
// baseline (speedup 1.0000x reference)
#include <cuda_runtime.h>
#include <cuda_bf16.h>

#define NQ  4
#define NL  5
#define DIM 16
#define NGATES (NL * NQ)

// ---------------------------------------------------------------------------
// Single fused persistent kernel.
// Phase A (60 threads): sincos of the 60 gate angles -> shared.
// Phase B (all 256 threads): propagate the 16 basis columns through the
//   circuit; thread (warp w, lane l) holds amplitude i = l&15 of column
//   j = 2w + (l>>4). Single-qubit gates exchange the partner amplitude via
//   shfl.xor (stride <= 8 stays inside the 16-lane half). Each layer's 4
//   CNOTs compose into one index permutation -> one shfl.idx pair.
//   Result: U[i][j] packed (re,im) in shared.
// Phase C (grid-stride over batch): s = a01 (x) a23 real product state;
//   psi = U s via packed fma.rn.f32x2 complex MACs (two chains per row),
//   |psi_i|^2, signed sums -> <Z_w>. Persistent blocks amortize A+B.
// ---------------------------------------------------------------------------
__global__ __launch_bounds__(256, 4) void qfused_kernel(
    const float* __restrict__ w,
    const float4* __restrict__ x,
    float4* __restrict__ out, int n)
{
    __shared__ float2 raw[NGATES][3];              // (sin, cos) per angle
    __shared__ unsigned long long sU[DIM * DIM];   // U[i][j] packed (re, im)

    const int tid = threadIdx.x;

    // ---- Phase A: gate-angle sincos, one thread per angle -----------------
    if (tid < NGATES * 3) {
        int g = tid / 3, k = tid - 3 * g;
        float phi = w[g * 3 + 0], th = w[g * 3 + 1], om = w[g * 3 + 2];
        float ang = (k == 0) ? -0.5f * (phi + om)
                  : (k == 1) ?  0.5f * (phi - om)
                             :  0.5f * th;
        float s, c;
        sincosf(ang, &s, &c);
        raw[g][k] = make_float2(s, c);
    }
    __syncthreads();

    // ---- Phase B: cooperative propagation of all 16 columns ---------------
    {
        int lane = tid & 31;
        int wrp  = tid >> 5;
        int j = 2 * wrp + (lane >> 4);   // column (basis input state)
        int i = lane & 15;               // amplitude index this thread owns

        float re = (i == j) ? 1.0f : 0.0f;
        float im = 0.0f;

        #pragma unroll
        for (int l = 0; l < NL; l++) {
            #pragma unroll
            for (int q = 0; q < NQ; q++) {
                int g = l * NQ + q;
                float2 P = raw[g][0];    // (sp, cp): e^{-i(phi+om)/2}
                float2 M = raw[g][1];    // (sm, cm): e^{+i(phi-om)/2}
                float2 T = raw[g][2];    // (st, ct): theta/2
                int stride = 8 >> q;     // qubit q lives at bit (3-q)
                bool hi = (i & stride) != 0;
                // self coeff: hi ? U11 : U00 ; partner coeff: hi ? U10 : U01
                float csx = P.y * T.y;
                float csy = (hi ? -P.x : P.x) * T.y;
                float cpx = (hi ?  M.y : -M.y) * T.x;
                float cpy = -M.x * T.x;
                float pre = __shfl_xor_sync(0xffffffffu, re, stride);
                float pim = __shfl_xor_sync(0xffffffffu, im, stride);
                float nre = csx * re - csy * im + cpx * pre - cpy * pim;
                float nim = csx * im + csy * re + cpx * pim + cpy * pre;
                re = nre; im = nim;
            }
            // Entangler: CNOT(q, (q+r)%4) for q=0..3 sequentially; composed:
            // st_new[i] = st_old[s0(s1(s2(s3(i))))]
            int r = (l % (NQ - 1)) + 1;
            int t = i;
            #pragma unroll
            for (int q = NQ - 1; q >= 0; q--) {
                int sc  = 8 >> q;
                int stt = 8 >> ((q + r) & 3);
                t = (t & sc) ? (t ^ stt) : t;
            }
            int src_lane = (lane & 16) | t;
            re = __shfl_sync(0xffffffffu, re, src_lane);
            im = __shfl_sync(0xffffffffu, im, src_lane);
        }

        unsigned long long packed;
        asm("mov.b64 %0, {%1, %2};" : "=l"(packed) : "f"(re), "f"(im));
        sU[i * DIM + j] = packed;
    }
    __syncthreads();

    // ---- Phase C: grid-stride per-element evaluation ----------------------
    const ulonglong2* sU2 = reinterpret_cast<const ulonglong2*>(sU);
    const int gstride = gridDim.x * blockDim.x;

    for (int b = blockIdx.x * blockDim.x + tid; b < n; b += gstride) {
        float4 xv = x[b];
        float s0, c0, s1, c1, s2, c2, s3, c3;
        __sincosf(0.5f * xv.x, &s0, &c0);
        __sincosf(0.5f * xv.y, &s1, &c1);
        __sincosf(0.5f * xv.z, &s2, &c2);
        __sincosf(0.5f * xv.w, &s3, &c3);

        float a01[4] = {c0 * c1, c0 * s1, s0 * c1, s0 * s1};
        float a23[4] = {c2 * c3, c2 * s3, s2 * c3, s2 * s3};

        // s[j] duplicated into both f32x2 lanes
        unsigned long long sd[DIM];
#pragma unroll
        for (int p = 0; p < 4; p++) {
#pragma unroll
            for (int q = 0; q < 4; q++) {
                float v = a01[p] * a23[q];
                unsigned long long d;
                asm("mov.b64 %0, {%1, %1};" : "=l"(d) : "f"(v));
                sd[p * 4 + q] = d;
            }
        }

        float z0 = 0.f, z1 = 0.f, z2 = 0.f, z3 = 0.f;
#pragma unroll
        for (int i = 0; i < DIM; i++) {
            // full row up-front (8 broadcast LDS.128, MLP)
            ulonglong2 u0 = sU2[i * 8 + 0];
            ulonglong2 u1 = sU2[i * 8 + 1];
            ulonglong2 u2 = sU2[i * 8 + 2];
            ulonglong2 u3 = sU2[i * 8 + 3];
            ulonglong2 u4 = sU2[i * 8 + 4];
            ulonglong2 u5 = sU2[i * 8 + 5];
            ulonglong2 u6 = sU2[i * 8 + 6];
            ulonglong2 u7 = sU2[i * 8 + 7];

            unsigned long long accA = 0ull, accB = 0ull;  // (0.0f, 0.0f)
            asm("fma.rn.f32x2 %0, %1, %2, %0;" : "+l"(accA) : "l"(u0.x), "l"(sd[0]));
            asm("fma.rn.f32x2 %0, %1, %2, %0;" : "+l"(accB) : "l"(u4.x), "l"(sd[8]));
            asm("fma.rn.f32x2 %0, %1, %2, %0;" : "+l"(accA) : "l"(u0.y), "l"(sd[1]));
            asm("fma.rn.f32x2 %0, %1, %2, %0;" : "+l"(accB) : "l"(u4.y), "l"(sd[9]));
            asm("fma.rn.f32x2 %0, %1, %2, %0;" : "+l"(accA) : "l"(u1.x), "l"(sd[2]));
            asm("fma.rn.f32x2 %0, %1, %2, %0;" : "+l"(accB) : "l"(u5.x), "l"(sd[10]));
            asm("fma.rn.f32x2 %0, %1, %2, %0;" : "+l"(accA) : "l"(u1.y), "l"(sd[3]));
            asm("fma.rn.f32x2 %0, %1, %2, %0;" : "+l"(accB) : "l"(u5.y), "l"(sd[11]));
            asm("fma.rn.f32x2 %0, %1, %2, %0;" : "+l"(accA) : "l"(u2.x), "l"(sd[4]));
            asm("fma.rn.f32x2 %0, %1, %2, %0;" : "+l"(accB) : "l"(u6.x), "l"(sd[12]));
            asm("fma.rn.f32x2 %0, %1, %2, %0;" : "+l"(accA) : "l"(u2.y), "l"(sd[5]));
            asm("fma.rn.f32x2 %0, %1, %2, %0;" : "+l"(accB) : "l"(u6.y), "l"(sd[13]));
            asm("fma.rn.f32x2 %0, %1, %2, %0;" : "+l"(accA) : "l"(u3.x), "l"(sd[6]));
            asm("fma.rn.f32x2 %0, %1, %2, %0;" : "+l"(accB) : "l"(u7.x), "l"(sd[14]));
            asm("fma.rn.f32x2 %0, %1, %2, %0;" : "+l"(accA) : "l"(u3.y), "l"(sd[7]));
            asm("fma.rn.f32x2 %0, %1, %2, %0;" : "+l"(accB) : "l"(u7.y), "l"(sd[15]));

            unsigned long long acc;
            asm("add.rn.f32x2 %0, %1, %2;" : "=l"(acc) : "l"(accA), "l"(accB));
            float pre, pim;
            asm("mov.b64 {%0, %1}, %2;" : "=f"(pre), "=f"(pim) : "l"(acc));
            float pv = pre * pre + pim * pim;

            z0 += (i & 8) ? -pv : pv;
            z1 += (i & 4) ? -pv : pv;
            z2 += (i & 2) ? -pv : pv;
            z3 += (i & 1) ? -pv : pv;
        }
        out[b] = make_float4(z0, z1, z2, z3);
    }
}

// ---------------------------------------------------------------------------
extern "C" void kernel_launch(void* const* d_in, const int* in_sizes, int n_in,
                              void* d_out, int out_size)
{
    const float* x;
    const float* w;
    int n;
    // disambiguate inputs by size (weights = 5*4*3 = 60 floats)
    if (in_sizes[0] == NL * NQ * 3) {
        w = (const float*)d_in[0];
        x = (const float*)d_in[1];
        n = in_sizes[1] / 4;
    } else {
        x = (const float*)d_in[0];
        w = (const float*)d_in[1];
        n = in_sizes[0] / 4;
    }

    int threads = 256;
    int blocks = (n + threads - 1) / threads;
    int persistent = 148 * 4;              // one full-occupancy wave
    if (blocks > persistent) blocks = persistent;
    qfused_kernel<<<blocks, threads>>>(w, (const float4*)x, (float4*)d_out, n);
}

// round 7
// speedup vs baseline: 1.1398x; 1.1398x over previous
#include <cuda_runtime.h>
#include <cuda_bf16.h>

#define NQ  4
#define NL  5
#define DIM 16
#define NGATES (NL * NQ)

// ---------------------------------------------------------------------------
// Single fused persistent kernel.
// Phase A (60 threads): sincos of the 60 gate angles -> shared.
// Phase B (all 256 threads): propagate the 16 basis columns through the
//   circuit via warp shuffles; write U in PLANAR (SoA) form: sUre / sUim.
// Phase C (grid-stride over batch): s = a01 (x) a23 real product state packed
//   as natural f32 pairs (8 regs); psi_i = (Ure_i . s) + i (Uim_i . s) via
//   packed fma.rn.f32x2 where each lane carries a DIFFERENT column -> no
//   operand duplication, no register spill. |psi_i|^2 signed-summed -> <Z_w>.
// ---------------------------------------------------------------------------
__global__ __launch_bounds__(256, 3) void qfused_kernel(
    const float* __restrict__ w,
    const float4* __restrict__ x,
    float4* __restrict__ out, int n)
{
    __shared__ float2 raw[NGATES][3];        // (sin, cos) per angle
    __shared__ float sUre[DIM * DIM];        // re(U[i][j]), row-major
    __shared__ float sUim[DIM * DIM];        // im(U[i][j]), row-major

    const int tid = threadIdx.x;

    // ---- Phase A: gate-angle sincos, one thread per angle -----------------
    if (tid < NGATES * 3) {
        int g = tid / 3, k = tid - 3 * g;
        float phi = w[g * 3 + 0], th = w[g * 3 + 1], om = w[g * 3 + 2];
        float ang = (k == 0) ? -0.5f * (phi + om)
                  : (k == 1) ?  0.5f * (phi - om)
                             :  0.5f * th;
        float s, c;
        sincosf(ang, &s, &c);
        raw[g][k] = make_float2(s, c);
    }
    __syncthreads();

    // ---- Phase B: cooperative propagation of all 16 columns ---------------
    {
        int lane = tid & 31;
        int wrp  = tid >> 5;
        int j = 2 * wrp + (lane >> 4);   // column (basis input state)
        int i = lane & 15;               // amplitude index this thread owns

        float re = (i == j) ? 1.0f : 0.0f;
        float im = 0.0f;

        #pragma unroll
        for (int l = 0; l < NL; l++) {
            #pragma unroll
            for (int q = 0; q < NQ; q++) {
                int g = l * NQ + q;
                float2 P = raw[g][0];    // (sp, cp): e^{-i(phi+om)/2}
                float2 M = raw[g][1];    // (sm, cm): e^{+i(phi-om)/2}
                float2 T = raw[g][2];    // (st, ct): theta/2
                int stride = 8 >> q;     // qubit q lives at bit (3-q)
                bool hi = (i & stride) != 0;
                // self coeff: hi ? U11 : U00 ; partner coeff: hi ? U10 : U01
                float csx = P.y * T.y;
                float csy = (hi ? -P.x : P.x) * T.y;
                float cpx = (hi ?  M.y : -M.y) * T.x;
                float cpy = -M.x * T.x;
                float pre = __shfl_xor_sync(0xffffffffu, re, stride);
                float pim = __shfl_xor_sync(0xffffffffu, im, stride);
                float nre = csx * re - csy * im + cpx * pre - cpy * pim;
                float nim = csx * im + csy * re + cpx * pim + cpy * pre;
                re = nre; im = nim;
            }
            // Entangler: CNOT(q, (q+r)%4) for q=0..3 sequentially; composed:
            // st_new[i] = st_old[s0(s1(s2(s3(i))))]
            int r = (l % (NQ - 1)) + 1;
            int t = i;
            #pragma unroll
            for (int q = NQ - 1; q >= 0; q--) {
                int sc  = 8 >> q;
                int stt = 8 >> ((q + r) & 3);
                t = (t & sc) ? (t ^ stt) : t;
            }
            int src_lane = (lane & 16) | t;
            re = __shfl_sync(0xffffffffu, re, src_lane);
            im = __shfl_sync(0xffffffffu, im, src_lane);
        }

        sUre[i * DIM + j] = re;
        sUim[i * DIM + j] = im;
    }
    __syncthreads();

    // ---- Phase C: grid-stride per-element evaluation ----------------------
    const ulonglong2* sRe2 = reinterpret_cast<const ulonglong2*>(sUre);
    const ulonglong2* sIm2 = reinterpret_cast<const ulonglong2*>(sUim);
    const int gstride = gridDim.x * blockDim.x;

    for (int b = blockIdx.x * blockDim.x + tid; b < n; b += gstride) {
        float4 xv = x[b];
        float s0, c0, s1, c1, s2, c2, s3, c3;
        __sincosf(0.5f * xv.x, &s0, &c0);
        __sincosf(0.5f * xv.y, &s1, &c1);
        __sincosf(0.5f * xv.z, &s2, &c2);
        __sincosf(0.5f * xv.w, &s3, &c3);

        float a01[4] = {c0 * c1, c0 * s1, s0 * c1, s0 * s1};
        float a23[4] = {c2 * c3, c2 * s3, s2 * c3, s2 * s3};

        // s packed as natural pairs: sp[j] = (s[2j], s[2j+1]) -> 8 regs only
        unsigned long long sp[8];
#pragma unroll
        for (int p = 0; p < 4; p++) {
            float vA = a01[p] * a23[0];
            float vB = a01[p] * a23[1];
            float vC = a01[p] * a23[2];
            float vD = a01[p] * a23[3];
            asm("mov.b64 %0, {%1, %2};" : "=l"(sp[2 * p    ]) : "f"(vA), "f"(vB));
            asm("mov.b64 %0, {%1, %2};" : "=l"(sp[2 * p + 1]) : "f"(vC), "f"(vD));
        }

        float z0 = 0.f, z1 = 0.f, z2 = 0.f, z3 = 0.f;
#pragma unroll
        for (int i = 0; i < DIM; i++) {
            // row i: 4 broadcast LDS.128 re + 4 im (each = 2 f32x2 operands)
            ulonglong2 r0 = sRe2[i * 4 + 0];
            ulonglong2 r1 = sRe2[i * 4 + 1];
            ulonglong2 r2 = sRe2[i * 4 + 2];
            ulonglong2 r3 = sRe2[i * 4 + 3];
            ulonglong2 m0 = sIm2[i * 4 + 0];
            ulonglong2 m1 = sIm2[i * 4 + 1];
            ulonglong2 m2 = sIm2[i * 4 + 2];
            ulonglong2 m3 = sIm2[i * 4 + 3];

            unsigned long long accRe = 0ull, accIm = 0ull;  // (0.0f, 0.0f)
            asm("fma.rn.f32x2 %0, %1, %2, %0;" : "+l"(accRe) : "l"(r0.x), "l"(sp[0]));
            asm("fma.rn.f32x2 %0, %1, %2, %0;" : "+l"(accIm) : "l"(m0.x), "l"(sp[0]));
            asm("fma.rn.f32x2 %0, %1, %2, %0;" : "+l"(accRe) : "l"(r0.y), "l"(sp[1]));
            asm("fma.rn.f32x2 %0, %1, %2, %0;" : "+l"(accIm) : "l"(m0.y), "l"(sp[1]));
            asm("fma.rn.f32x2 %0, %1, %2, %0;" : "+l"(accRe) : "l"(r1.x), "l"(sp[2]));
            asm("fma.rn.f32x2 %0, %1, %2, %0;" : "+l"(accIm) : "l"(m1.x), "l"(sp[2]));
            asm("fma.rn.f32x2 %0, %1, %2, %0;" : "+l"(accRe) : "l"(r1.y), "l"(sp[3]));
            asm("fma.rn.f32x2 %0, %1, %2, %0;" : "+l"(accIm) : "l"(m1.y), "l"(sp[3]));
            asm("fma.rn.f32x2 %0, %1, %2, %0;" : "+l"(accRe) : "l"(r2.x), "l"(sp[4]));
            asm("fma.rn.f32x2 %0, %1, %2, %0;" : "+l"(accIm) : "l"(m2.x), "l"(sp[4]));
            asm("fma.rn.f32x2 %0, %1, %2, %0;" : "+l"(accRe) : "l"(r2.y), "l"(sp[5]));
            asm("fma.rn.f32x2 %0, %1, %2, %0;" : "+l"(accIm) : "l"(m2.y), "l"(sp[5]));
            asm("fma.rn.f32x2 %0, %1, %2, %0;" : "+l"(accRe) : "l"(r3.x), "l"(sp[6]));
            asm("fma.rn.f32x2 %0, %1, %2, %0;" : "+l"(accIm) : "l"(m3.x), "l"(sp[6]));
            asm("fma.rn.f32x2 %0, %1, %2, %0;" : "+l"(accRe) : "l"(r3.y), "l"(sp[7]));
            asm("fma.rn.f32x2 %0, %1, %2, %0;" : "+l"(accIm) : "l"(m3.y), "l"(sp[7]));

            float reL, reH, imL, imH;
            asm("mov.b64 {%0, %1}, %2;" : "=f"(reL), "=f"(reH) : "l"(accRe));
            asm("mov.b64 {%0, %1}, %2;" : "=f"(imL), "=f"(imH) : "l"(accIm));
            float re = reL + reH;
            float im = imL + imH;
            float pv = re * re + im * im;

            z0 += (i & 8) ? -pv : pv;
            z1 += (i & 4) ? -pv : pv;
            z2 += (i & 2) ? -pv : pv;
            z3 += (i & 1) ? -pv : pv;
        }
        out[b] = make_float4(z0, z1, z2, z3);
    }
}

// ---------------------------------------------------------------------------
extern "C" void kernel_launch(void* const* d_in, const int* in_sizes, int n_in,
                              void* d_out, int out_size)
{
    const float* x;
    const float* w;
    int n;
    // disambiguate inputs by size (weights = 5*4*3 = 60 floats)
    if (in_sizes[0] == NL * NQ * 3) {
        w = (const float*)d_in[0];
        x = (const float*)d_in[1];
        n = in_sizes[1] / 4;
    } else {
        x = (const float*)d_in[0];
        w = (const float*)d_in[1];
        n = in_sizes[0] / 4;
    }

    int threads = 256;
    int blocks = (n + threads - 1) / threads;
    int persistent = 148 * 4;              // one full-occupancy wave
    if (blocks > persistent) blocks = persistent;
    qfused_kernel<<<blocks, threads>>>(w, (const float4*)x, (float4*)d_out, n);
}

// round 12
// speedup vs baseline: 7.2724x; 6.3807x over previous
#include <cuda_runtime.h>
#include <cuda_bf16.h>

#define NQ  4
#define NL  5
#define DIM 16
#define NGATES (NL * NQ)

// ---------------------------------------------------------------------------
// Single fused kernel, one element per thread (1024 blocks x 256 threads).
// Phase A (60 threads): sincos of the 60 gate angles -> shared.
// Phase B (all threads): propagate the 16 basis columns through the circuit
//   via warp shuffles (each warp handles 2 columns); U -> shared, AoS packed
//   (re,im) per entry.
// Phase C: round-1 validated structure verbatim — s = a01 (x) a23 product
//   state duplicated into f32x2 lanes, psi = U s with inline LDS.128 loads
//   and a single fma.rn.f32x2 chain per row (53-reg, spill-free profile).
// ---------------------------------------------------------------------------
__global__ __launch_bounds__(256) void qfused_kernel(
    const float* __restrict__ w,
    const float4* __restrict__ x,
    float4* __restrict__ out, int n)
{
    __shared__ float2 raw[NGATES][3];              // (sin, cos) per angle
    __shared__ unsigned long long sU[DIM * DIM];   // U[i][j] packed (re, im)

    const int tid = threadIdx.x;

    // ---- Phase A: gate-angle sincos, one thread per angle -----------------
    if (tid < NGATES * 3) {
        int g = tid / 3, k = tid - 3 * g;
        float phi = w[g * 3 + 0], th = w[g * 3 + 1], om = w[g * 3 + 2];
        float ang = (k == 0) ? -0.5f * (phi + om)
                  : (k == 1) ?  0.5f * (phi - om)
                             :  0.5f * th;
        float s, c;
        sincosf(ang, &s, &c);
        raw[g][k] = make_float2(s, c);
    }
    __syncthreads();

    // ---- Phase B: cooperative propagation of all 16 columns ---------------
    {
        int lane = tid & 31;
        int wrp  = tid >> 5;
        int j = 2 * wrp + (lane >> 4);   // column (basis input state)
        int i = lane & 15;               // amplitude index this thread owns

        float re = (i == j) ? 1.0f : 0.0f;
        float im = 0.0f;

        #pragma unroll
        for (int l = 0; l < NL; l++) {
            #pragma unroll
            for (int q = 0; q < NQ; q++) {
                int g = l * NQ + q;
                float2 P = raw[g][0];    // (sp, cp): e^{-i(phi+om)/2}
                float2 M = raw[g][1];    // (sm, cm): e^{+i(phi-om)/2}
                float2 T = raw[g][2];    // (st, ct): theta/2
                int stride = 8 >> q;     // qubit q lives at bit (3-q)
                bool hi = (i & stride) != 0;
                // self coeff: hi ? U11 : U00 ; partner coeff: hi ? U10 : U01
                float csx = P.y * T.y;
                float csy = (hi ? -P.x : P.x) * T.y;
                float cpx = (hi ?  M.y : -M.y) * T.x;
                float cpy = -M.x * T.x;
                float pre = __shfl_xor_sync(0xffffffffu, re, stride);
                float pim = __shfl_xor_sync(0xffffffffu, im, stride);
                float nre = csx * re - csy * im + cpx * pre - cpy * pim;
                float nim = csx * im + csy * re + cpx * pim + cpy * pre;
                re = nre; im = nim;
            }
            // Entangler: CNOT(q, (q+r)%4) for q=0..3 sequentially; composed:
            // st_new[i] = st_old[s0(s1(s2(s3(i))))]
            int r = (l % (NQ - 1)) + 1;
            int t = i;
            #pragma unroll
            for (int q = NQ - 1; q >= 0; q--) {
                int sc  = 8 >> q;
                int stt = 8 >> ((q + r) & 3);
                t = (t & sc) ? (t ^ stt) : t;
            }
            int src_lane = (lane & 16) | t;
            re = __shfl_sync(0xffffffffu, re, src_lane);
            im = __shfl_sync(0xffffffffu, im, src_lane);
        }

        unsigned long long packed;
        asm("mov.b64 %0, {%1, %2};" : "=l"(packed) : "f"(re), "f"(im));
        sU[i * DIM + j] = packed;
    }
    __syncthreads();

    // ---- Phase C: per-element evaluation (round-1 validated structure) ----
    int b = blockIdx.x * blockDim.x + tid;
    if (b >= n) return;

    float4 xv = x[b];
    float s0, c0, s1, c1, s2, c2, s3, c3;
    __sincosf(0.5f * xv.x, &s0, &c0);
    __sincosf(0.5f * xv.y, &s1, &c1);
    __sincosf(0.5f * xv.z, &s2, &c2);
    __sincosf(0.5f * xv.w, &s3, &c3);

    float a01[4] = {c0 * c1, c0 * s1, s0 * c1, s0 * s1};
    float a23[4] = {c2 * c3, c2 * s3, s2 * c3, s2 * s3};

    // s[j] duplicated into both f32x2 lanes
    unsigned long long sd[DIM];
#pragma unroll
    for (int p = 0; p < 4; p++) {
#pragma unroll
        for (int q = 0; q < 4; q++) {
            float v = a01[p] * a23[q];
            unsigned long long d;
            asm("mov.b64 %0, {%1, %1};" : "=l"(d) : "f"(v));
            sd[p * 4 + q] = d;
        }
    }

    const ulonglong2* sU2 = reinterpret_cast<const ulonglong2*>(sU);

    float prob[DIM];
#pragma unroll
    for (int i = 0; i < DIM; i++) {
        unsigned long long acc = 0ull;   // (0.0f, 0.0f)
#pragma unroll
        for (int jj = 0; jj < 8; jj++) {
            ulonglong2 u2 = sU2[i * 8 + jj];   // broadcast LDS.128, inline
            asm("fma.rn.f32x2 %0, %1, %2, %0;" : "+l"(acc) : "l"(u2.x), "l"(sd[2 * jj    ]));
            asm("fma.rn.f32x2 %0, %1, %2, %0;" : "+l"(acc) : "l"(u2.y), "l"(sd[2 * jj + 1]));
        }
        float re, im;
        asm("mov.b64 {%0, %1}, %2;" : "=f"(re), "=f"(im) : "l"(acc));
        prob[i] = re * re + im * im;
    }

    float z0 = 0.f, z1 = 0.f, z2 = 0.f, z3 = 0.f;
#pragma unroll
    for (int i = 0; i < DIM; i++) {
        float pv = prob[i];
        z0 += (i & 8) ? -pv : pv;
        z1 += (i & 4) ? -pv : pv;
        z2 += (i & 2) ? -pv : pv;
        z3 += (i & 1) ? -pv : pv;
    }
    out[b] = make_float4(z0, z1, z2, z3);
}

// ---------------------------------------------------------------------------
extern "C" void kernel_launch(void* const* d_in, const int* in_sizes, int n_in,
                              void* d_out, int out_size)
{
    const float* x;
    const float* w;
    int n;
    // disambiguate inputs by size (weights = 5*4*3 = 60 floats)
    if (in_sizes[0] == NL * NQ * 3) {
        w = (const float*)d_in[0];
        x = (const float*)d_in[1];
        n = in_sizes[1] / 4;
    } else {
        x = (const float*)d_in[0];
        w = (const float*)d_in[1];
        n = in_sizes[0] / 4;
    }

    int threads = 256;
    int blocks = (n + threads - 1) / threads;
    qfused_kernel<<<blocks, threads>>>(w, (const float4*)x, (float4*)d_out, n);
}

// round 15
// speedup vs baseline: 8.1556x; 1.1214x over previous
#include <cuda_runtime.h>
#include <cuda_bf16.h>

#define NQ  4
#define NL  5
#define DIM 16
#define NGATES (NL * NQ)

// Circuit unitary, built once by build kernel: U[i][j] packed (re, im).
__device__ unsigned long long g_U[DIM * DIM];

// ---------------------------------------------------------------------------
// Build kernel: ONE block of 256 threads.
// Phase A (60 threads): sincos of the 60 gate angles -> shared.
// Phase B (all threads): propagate the 16 basis columns through the circuit
//   via warp shuffles (each warp handles 2 columns). Writes g_U.
// ---------------------------------------------------------------------------
__global__ __launch_bounds__(256) void build_kernel(const float* __restrict__ w)
{
    __shared__ float2 raw[NGATES][3];              // (sin, cos) per angle

    const int tid = threadIdx.x;

    if (tid < NGATES * 3) {
        int g = tid / 3, k = tid - 3 * g;
        float phi = w[g * 3 + 0], th = w[g * 3 + 1], om = w[g * 3 + 2];
        float ang = (k == 0) ? -0.5f * (phi + om)
                  : (k == 1) ?  0.5f * (phi - om)
                             :  0.5f * th;
        float s, c;
        sincosf(ang, &s, &c);
        raw[g][k] = make_float2(s, c);
    }
    __syncthreads();

    int lane = tid & 31;
    int wrp  = tid >> 5;
    int j = 2 * wrp + (lane >> 4);   // column (basis input state)
    int i = lane & 15;               // amplitude index this thread owns

    float re = (i == j) ? 1.0f : 0.0f;
    float im = 0.0f;

    #pragma unroll
    for (int l = 0; l < NL; l++) {
        #pragma unroll
        for (int q = 0; q < NQ; q++) {
            int g = l * NQ + q;
            float2 P = raw[g][0];    // (sp, cp): e^{-i(phi+om)/2}
            float2 M = raw[g][1];    // (sm, cm): e^{+i(phi-om)/2}
            float2 T = raw[g][2];    // (st, ct): theta/2
            int stride = 8 >> q;     // qubit q lives at bit (3-q)
            bool hi = (i & stride) != 0;
            // self coeff: hi ? U11 : U00 ; partner coeff: hi ? U10 : U01
            float csx = P.y * T.y;
            float csy = (hi ? -P.x : P.x) * T.y;
            float cpx = (hi ?  M.y : -M.y) * T.x;
            float cpy = -M.x * T.x;
            float pre = __shfl_xor_sync(0xffffffffu, re, stride);
            float pim = __shfl_xor_sync(0xffffffffu, im, stride);
            float nre = csx * re - csy * im + cpx * pre - cpy * pim;
            float nim = csx * im + csy * re + cpx * pim + cpy * pre;
            re = nre; im = nim;
        }
        // Entangler: CNOT(q, (q+r)%4) for q=0..3 sequentially; composed:
        // st_new[i] = st_old[s0(s1(s2(s3(i))))]
        int r = (l % (NQ - 1)) + 1;
        int t = i;
        #pragma unroll
        for (int q = NQ - 1; q >= 0; q--) {
            int sc  = 8 >> q;
            int stt = 8 >> ((q + r) & 3);
            t = (t & sc) ? (t ^ stt) : t;
        }
        int src_lane = (lane & 16) | t;
        re = __shfl_sync(0xffffffffu, re, src_lane);
        im = __shfl_sync(0xffffffffu, im, src_lane);
    }

    unsigned long long packed;
    asm("mov.b64 %0, {%1, %2};" : "=l"(packed) : "f"(re), "f"(im));
    g_U[i * DIM + j] = packed;
}

// ---------------------------------------------------------------------------
// Main kernel: one element per thread. Copies the 2KB U from gmem (L2-hot)
// into shared (1 LDG.64 + 1 STS per thread), then runs the validated
// round-1 Phase C verbatim (inline LDS.128, single f32x2 chain, 56 regs).
// ---------------------------------------------------------------------------
__global__ __launch_bounds__(256) void qmain_kernel(
    const float4* __restrict__ x, float4* __restrict__ out, int n)
{
    __shared__ unsigned long long sU[DIM * DIM];   // U[i][j] packed (re, im)

    const int tid = threadIdx.x;
    sU[tid] = g_U[tid];                            // 256 entries, 1 per thread
    __syncthreads();

    int b = blockIdx.x * blockDim.x + tid;
    if (b >= n) return;

    float4 xv = x[b];
    float s0, c0, s1, c1, s2, c2, s3, c3;
    __sincosf(0.5f * xv.x, &s0, &c0);
    __sincosf(0.5f * xv.y, &s1, &c1);
    __sincosf(0.5f * xv.z, &s2, &c2);
    __sincosf(0.5f * xv.w, &s3, &c3);

    float a01[4] = {c0 * c1, c0 * s1, s0 * c1, s0 * s1};
    float a23[4] = {c2 * c3, c2 * s3, s2 * c3, s2 * s3};

    // s[j] duplicated into both f32x2 lanes
    unsigned long long sd[DIM];
#pragma unroll
    for (int p = 0; p < 4; p++) {
#pragma unroll
        for (int q = 0; q < 4; q++) {
            float v = a01[p] * a23[q];
            unsigned long long d;
            asm("mov.b64 %0, {%1, %1};" : "=l"(d) : "f"(v));
            sd[p * 4 + q] = d;
        }
    }

    const ulonglong2* sU2 = reinterpret_cast<const ulonglong2*>(sU);

    float prob[DIM];
#pragma unroll
    for (int i = 0; i < DIM; i++) {
        unsigned long long acc = 0ull;   // (0.0f, 0.0f)
#pragma unroll
        for (int jj = 0; jj < 8; jj++) {
            ulonglong2 u2 = sU2[i * 8 + jj];   // broadcast LDS.128, inline
            asm("fma.rn.f32x2 %0, %1, %2, %0;" : "+l"(acc) : "l"(u2.x), "l"(sd[2 * jj    ]));
            asm("fma.rn.f32x2 %0, %1, %2, %0;" : "+l"(acc) : "l"(u2.y), "l"(sd[2 * jj + 1]));
        }
        float re, im;
        asm("mov.b64 {%0, %1}, %2;" : "=f"(re), "=f"(im) : "l"(acc));
        prob[i] = re * re + im * im;
    }

    float z0 = 0.f, z1 = 0.f, z2 = 0.f, z3 = 0.f;
#pragma unroll
    for (int i = 0; i < DIM; i++) {
        float pv = prob[i];
        z0 += (i & 8) ? -pv : pv;
        z1 += (i & 4) ? -pv : pv;
        z2 += (i & 2) ? -pv : pv;
        z3 += (i & 1) ? -pv : pv;
    }
    out[b] = make_float4(z0, z1, z2, z3);
}

// ---------------------------------------------------------------------------
extern "C" void kernel_launch(void* const* d_in, const int* in_sizes, int n_in,
                              void* d_out, int out_size)
{
    const float* x;
    const float* w;
    int n;
    // disambiguate inputs by size (weights = 5*4*3 = 60 floats)
    if (in_sizes[0] == NL * NQ * 3) {
        w = (const float*)d_in[0];
        x = (const float*)d_in[1];
        n = in_sizes[1] / 4;
    } else {
        x = (const float*)d_in[0];
        w = (const float*)d_in[1];
        n = in_sizes[0] / 4;
    }

    build_kernel<<<1, 256>>>(w);

    int threads = 256;
    int blocks = (n + threads - 1) / threads;
    qmain_kernel<<<blocks, threads>>>((const float4*)x, (float4*)d_out, n);
}